// round 3
// baseline (speedup 1.0000x reference)
#include <cuda_runtime.h>

#define NNODES 100000
#define NEDGES 1600000
#define CH 128
#define NGRAPH 256
#define BM 128
#define BK 32
#define SCAN_B 512

// ---------------- scratch (device globals; no allocations allowed) ----------------
__device__ float g_H[(size_t)NNODES * CH];   // GEMM output (h = A @ W)
__device__ float g_G[(size_t)NNODES * CH];   // conv output (post agg+bias+relu)
__device__ int   g_deg[NNODES];              // in-edge count (excl. self loop)
__device__ float g_dis[NNODES];              // (1+deg)^-0.5
__device__ float g_inv[NNODES];              // 1/(1+deg)
__device__ int   g_off[NNODES];              // CSR exclusive offsets
__device__ int   g_pos[NNODES];              // scatter cursors (mutable copy of off)
__device__ int   g_csr[NEDGES];              // src node per CSR slot
__device__ int   g_part[SCAN_B];             // scan partials
__device__ float g_gsum[NGRAPH * CH];
__device__ int   g_gcnt[NGRAPH];

// ---------------- init: zero deg / pooling buffers ----------------
__global__ void k_init(int n) {
    int i = blockIdx.x * blockDim.x + threadIdx.x;
    if (i < n) g_deg[i] = 0;
    if (i < NGRAPH * CH) g_gsum[i] = 0.f;
    if (i < NGRAPH) g_gcnt[i] = 0;
}

// ---------------- degree histogram ----------------
__global__ void k_count(const int* __restrict__ dst, int E) {
    int e = blockIdx.x * blockDim.x + threadIdx.x;
    if (e < E) atomicAdd(&g_deg[dst[e]], 1);
}

// ---------------- degree finalize + graph node counts ----------------
__global__ void k_degfin(const int* __restrict__ batch, int n) {
    int i = blockIdx.x * blockDim.x + threadIdx.x;
    if (i >= n) return;
    float d = 1.0f + (float)g_deg[i];
    g_dis[i] = rsqrtf(d);
    g_inv[i] = 1.0f / d;
    atomicAdd(&g_gcnt[batch[i]], 1);
}

// ---------------- 3-kernel exclusive scan of g_deg -> g_off ----------------
__global__ void k_scan1(int n) {
    __shared__ int s[SCAN_B];
    int tid = threadIdx.x;
    int i = blockIdx.x * SCAN_B + tid;
    int v = (i < n) ? g_deg[i] : 0;
    s[tid] = v;
    __syncthreads();
    #pragma unroll
    for (int d = 1; d < SCAN_B; d <<= 1) {
        int t = (tid >= d) ? s[tid - d] : 0;
        __syncthreads();
        s[tid] += t;
        __syncthreads();
    }
    if (i < n) g_off[i] = s[tid];              // inclusive-within-block (temp)
    if (tid == SCAN_B - 1) g_part[blockIdx.x] = s[tid];
}

__global__ void k_scan2(int nb) {
    __shared__ int s[256];
    int tid = threadIdx.x;
    int v = (tid < nb) ? g_part[tid] : 0;
    s[tid] = v;
    __syncthreads();
    #pragma unroll
    for (int d = 1; d < 256; d <<= 1) {
        int t = (tid >= d) ? s[tid - d] : 0;
        __syncthreads();
        s[tid] += t;
        __syncthreads();
    }
    if (tid < nb) g_part[tid] = s[tid] - v;    // exclusive
}

__global__ void k_scan3(int n) {
    int i = blockIdx.x * blockDim.x + threadIdx.x;
    if (i >= n) return;
    int excl = g_off[i] - g_deg[i] + g_part[i / SCAN_B];
    g_off[i] = excl;
    g_pos[i] = excl;
}

// ---------------- CSR scatter ----------------
__global__ void k_scatter(const int* __restrict__ src, const int* __restrict__ dst, int E) {
    int e = blockIdx.x * blockDim.x + threadIdx.x;
    if (e >= E) return;
    int d = dst[e];
    int p = atomicAdd(&g_pos[d], 1);
    g_csr[p] = src[e];
}

// ---------------- GEMM: g_H = A @ W,  A is [M,128], W is [128,128] ----------------
// block = 256 threads (16x16), tile 128 rows x 128 cols, K in chunks of 32.
// Static smem: As (transposed) 32x132 + Ws 32x128 = 33.3 KB -> no opt-in needed.
__global__ void __launch_bounds__(256) k_gemm(const float* __restrict__ Aext,
                                              const float* __restrict__ W,
                                              int M, int useG) {
    __shared__ float As[BK][BM + 4];   // As[k][m]
    __shared__ float Ws[BK][CH];       // Ws[k][n]
    const float* __restrict__ A = useG ? g_G : Aext;

    int tid = threadIdx.x;
    int row0 = blockIdx.x * BM;
    int tx = tid & 15, ty = tid >> 4;        // 16 x 16
    int rbase = ty * 8, cbase = tx * 8;

    float acc[8][8];
    #pragma unroll
    for (int r = 0; r < 8; r++)
        #pragma unroll
        for (int c = 0; c < 8; c++) acc[r][c] = 0.f;

    for (int k0 = 0; k0 < CH; k0 += BK) {
        // load A chunk: 128 rows x 32 k, transposed into As[k][m]
        {
            int q = tid & 7;            // which float4 within the 32-k chunk
            int m0 = tid >> 3;          // 32 rows per pass
            #pragma unroll
            for (int p = 0; p < 4; p++) {
                int m = m0 + p * 32;
                int row = row0 + m;
                float4 v = make_float4(0.f, 0.f, 0.f, 0.f);
                if (row < M) v = *(const float4*)&A[(size_t)row * CH + k0 + q * 4];
                As[q * 4 + 0][m] = v.x;
                As[q * 4 + 1][m] = v.y;
                As[q * 4 + 2][m] = v.z;
                As[q * 4 + 3][m] = v.w;
            }
        }
        // load W chunk: 32 k x 128 n
        {
            int n4 = tid & 31;
            int kk0 = tid >> 5;         // 8 k-rows per pass
            #pragma unroll
            for (int p = 0; p < 4; p++) {
                int kk = kk0 + p * 8;
                *(float4*)&Ws[kk][n4 * 4] = *(const float4*)&W[(size_t)(k0 + kk) * CH + n4 * 4];
            }
        }
        __syncthreads();

        #pragma unroll
        for (int kk = 0; kk < BK; kk++) {
            float av[8], wv[8];
            #pragma unroll
            for (int r = 0; r < 8; r++) av[r] = As[kk][rbase + r];
            #pragma unroll
            for (int c = 0; c < 8; c++) wv[c] = Ws[kk][cbase + c];
            #pragma unroll
            for (int r = 0; r < 8; r++)
                #pragma unroll
                for (int c = 0; c < 8; c++)
                    acc[r][c] = fmaf(av[r], wv[c], acc[r][c]);
        }
        __syncthreads();
    }

    #pragma unroll
    for (int r = 0; r < 8; r++) {
        int row = row0 + rbase + r;
        if (row < M) {
            float4 o0 = make_float4(acc[r][0], acc[r][1], acc[r][2], acc[r][3]);
            float4 o1 = make_float4(acc[r][4], acc[r][5], acc[r][6], acc[r][7]);
            *(float4*)&g_H[(size_t)row * CH + cbase] = o0;
            *(float4*)&g_H[(size_t)row * CH + cbase + 4] = o1;
        }
    }
}

// ---------------- aggregation: warp per node, lane = 4 channels ----------------
// out_i = relu( dis_i * sum_e dis[src]*h[src]  +  h_i/deg_i  +  bias )
// do_pool: atomically accumulate into per-graph sums instead of storing rows.
__global__ void k_agg(const float* __restrict__ bias, const int* __restrict__ batch,
                      int n, int do_pool) {
    int gw = (blockIdx.x * blockDim.x + threadIdx.x) >> 5;
    int lane = threadIdx.x & 31;
    if (gw >= n) return;
    int i = gw;
    int s = g_off[i];
    int e = s + g_deg[i];
    float ax = 0.f, ay = 0.f, az = 0.f, aw = 0.f;
    int col = lane * 4;
    for (int p = s; p < e; p++) {
        int src = __ldg(&g_csr[p]);
        float w = __ldg(&g_dis[src]);
        float4 hv = *(const float4*)&g_H[(size_t)src * CH + col];
        ax = fmaf(w, hv.x, ax);
        ay = fmaf(w, hv.y, ay);
        az = fmaf(w, hv.z, az);
        aw = fmaf(w, hv.w, aw);
    }
    float di = g_dis[i], iv = g_inv[i];
    float4 hi = *(const float4*)&g_H[(size_t)i * CH + col];
    float4 b  = *(const float4*)&bias[col];
    float rx = fmaxf(fmaf(di, ax, fmaf(iv, hi.x, b.x)), 0.f);
    float ry = fmaxf(fmaf(di, ay, fmaf(iv, hi.y, b.y)), 0.f);
    float rz = fmaxf(fmaf(di, az, fmaf(iv, hi.z, b.z)), 0.f);
    float rw = fmaxf(fmaf(di, aw, fmaf(iv, hi.w, b.w)), 0.f);
    if (do_pool) {
        int g = batch[i];
        float* gp = &g_gsum[g * CH + col];
        atomicAdd(gp + 0, rx);
        atomicAdd(gp + 1, ry);
        atomicAdd(gp + 2, rz);
        atomicAdd(gp + 3, rw);
    } else {
        *(float4*)&g_G[(size_t)i * CH + col] = make_float4(rx, ry, rz, rw);
    }
}

// ---------------- final: per-graph mean-pool dot with Wfc ----------------
__global__ void k_final(const float* __restrict__ Wfc, const float* __restrict__ bfc,
                        float* __restrict__ out) {
    int g = (blockIdx.x * blockDim.x + threadIdx.x) >> 5;
    int lane = threadIdx.x & 31;
    if (g >= NGRAPH) return;
    float4 gs = *(const float4*)&g_gsum[g * CH + lane * 4];
    float4 wf = *(const float4*)&Wfc[lane * 4];
    float s = gs.x * wf.x + gs.y * wf.y + gs.z * wf.z + gs.w * wf.w;
    #pragma unroll
    for (int o = 16; o; o >>= 1) s += __shfl_xor_sync(0xFFFFFFFFu, s, o);
    if (lane == 0) {
        float c = (float)(g_gcnt[g] > 1 ? g_gcnt[g] : 1);
        out[g] = s / c + bfc[0];
    }
}

// ---------------- host ----------------
extern "C" void kernel_launch(void* const* d_in, const int* in_sizes, int n_in,
                              void* d_out, int out_size) {
    const float* x     = (const float*)d_in[0];
    const int*   ei    = (const int*)  d_in[1];
    const int*   batch = (const int*)  d_in[2];
    const float* W1    = (const float*)d_in[3];
    const float* b1    = (const float*)d_in[4];
    const float* W2    = (const float*)d_in[5];
    const float* b2    = (const float*)d_in[6];
    const float* Wfc   = (const float*)d_in[7];
    const float* bfc   = (const float*)d_in[8];
    float* out = (float*)d_out;

    int n = in_sizes[0] / CH;       // 100000
    int E = in_sizes[1] / 2;        // 1600000
    const int* srcp = ei;
    const int* dstp = ei + E;

    int nb256 = (n + 255) / 256;
    int eb256 = (E + 255) / 256;
    int nbS   = (n + SCAN_B - 1) / SCAN_B;

    // graph structure (recomputed every launch; deterministic)
    k_init  <<<nb256, 256>>>(n);
    k_count <<<eb256, 256>>>(dstp, E);
    k_degfin<<<nb256, 256>>>(batch, n);
    k_scan1 <<<nbS, SCAN_B>>>(n);
    k_scan2 <<<1, 256>>>(nbS);
    k_scan3 <<<nb256, 256>>>(n);
    k_scatter<<<eb256, 256>>>(srcp, dstp, E);

    int gemm_blocks = (n + BM - 1) / BM;
    int agg_blocks  = (n * 32 + 255) / 256;

    // layer 1: h = x@W1 ; agg+bias+relu -> g_G
    k_gemm<<<gemm_blocks, 256>>>(x, W1, n, 0);
    k_agg <<<agg_blocks, 256>>>(b1, batch, n, 0);

    // layer 2: h = g_G@W2 ; agg+bias+relu fused with mean-pool accumulate
    k_gemm<<<gemm_blocks, 256>>>(x, W2, n, 1);
    k_agg <<<agg_blocks, 256>>>(b2, batch, n, 1);

    // readout
    k_final<<<32, 256>>>(Wfc, bfc, out);
}

// round 7
// speedup vs baseline: 1.2886x; 1.2886x over previous
#include <cuda_runtime.h>
#include <cstdint>

#define NNODES 100000
#define NEDGES 1600000
#define CH 128
#define NGRAPH 256
#define SCAN_B 512
#define PADA 36
#define PADW 136   // 128 cols + 8 pad -> stride%32==8 -> conflict-free B-frag reads

// ---------------- scratch (device globals; no allocations allowed) ----------------
__device__ float g_H[(size_t)NNODES * CH];   // GEMM output (h = A @ W)
__device__ float g_G[(size_t)NNODES * CH];   // conv output (post agg+bias+relu)
__device__ int   g_deg[NNODES];              // in-edge count (excl. self loop)
__device__ float g_dis[NNODES];              // (1+deg)^-0.5
__device__ float g_inv[NNODES];              // 1/(1+deg)
__device__ int   g_off[NNODES];              // CSR exclusive offsets
__device__ int   g_pos[NNODES];              // scatter cursors
__device__ int   g_csr[NEDGES];              // src node per CSR slot
__device__ int   g_part[SCAN_B];             // scan partials
__device__ float g_gsum[NGRAPH * CH];
__device__ int   g_gcnt[NGRAPH];

// ---------------- init: zero deg / pooling buffers ----------------
__global__ void k_init(int n) {
    int i = blockIdx.x * blockDim.x + threadIdx.x;
    if (i < n) g_deg[i] = 0;
    if (i < NGRAPH * CH) g_gsum[i] = 0.f;
    if (i < NGRAPH) g_gcnt[i] = 0;
}

// ---------------- degree histogram ----------------
__global__ void k_count(const int* __restrict__ dst, int E) {
    int e = blockIdx.x * blockDim.x + threadIdx.x;
    if (e < E) atomicAdd(&g_deg[dst[e]], 1);
}

// ---------------- degree finalize + graph node counts ----------------
__global__ void k_degfin(const int* __restrict__ batch, int n) {
    int i = blockIdx.x * blockDim.x + threadIdx.x;
    if (i >= n) return;
    float d = 1.0f + (float)g_deg[i];
    g_dis[i] = rsqrtf(d);
    g_inv[i] = 1.0f / d;
    atomicAdd(&g_gcnt[batch[i]], 1);
}

// ---------------- 3-kernel exclusive scan of g_deg -> g_off ----------------
__global__ void k_scan1(int n) {
    __shared__ int s[SCAN_B];
    int tid = threadIdx.x;
    int i = blockIdx.x * SCAN_B + tid;
    int v = (i < n) ? g_deg[i] : 0;
    s[tid] = v;
    __syncthreads();
    #pragma unroll
    for (int d = 1; d < SCAN_B; d <<= 1) {
        int t = (tid >= d) ? s[tid - d] : 0;
        __syncthreads();
        s[tid] += t;
        __syncthreads();
    }
    if (i < n) g_off[i] = s[tid];              // inclusive-within-block (temp)
    if (tid == SCAN_B - 1) g_part[blockIdx.x] = s[tid];
}

__global__ void k_scan2(int nb) {
    __shared__ int s[256];
    int tid = threadIdx.x;
    int v = (tid < nb) ? g_part[tid] : 0;
    s[tid] = v;
    __syncthreads();
    #pragma unroll
    for (int d = 1; d < 256; d <<= 1) {
        int t = (tid >= d) ? s[tid - d] : 0;
        __syncthreads();
        s[tid] += t;
        __syncthreads();
    }
    if (tid < nb) g_part[tid] = s[tid] - v;    // exclusive
}

__global__ void k_scan3(int n) {
    int i = blockIdx.x * blockDim.x + threadIdx.x;
    if (i >= n) return;
    int excl = g_off[i] - g_deg[i] + g_part[i / SCAN_B];
    g_off[i] = excl;
    g_pos[i] = excl;
}

// ---------------- CSR scatter ----------------
__global__ void k_scatter(const int* __restrict__ src, const int* __restrict__ dst, int E) {
    int e = blockIdx.x * blockDim.x + threadIdx.x;
    if (e >= E) return;
    int d = dst[e];
    int p = atomicAdd(&g_pos[d], 1);
    g_csr[p] = src[e];
}

// ---------------- tf32 helpers ----------------
__device__ __forceinline__ uint32_t f2tf32(float f) {
    uint32_t u;
    asm("cvt.rna.tf32.f32 %0, %1;" : "=r"(u) : "f"(f));
    return u;
}

__device__ __forceinline__ void mma_tf32(float* c, uint32_t a0, uint32_t a1,
                                         uint32_t a2, uint32_t a3,
                                         uint32_t b0, uint32_t b1) {
    asm volatile(
        "mma.sync.aligned.m16n8k8.row.col.f32.tf32.tf32.f32 "
        "{%0,%1,%2,%3}, {%4,%5,%6,%7}, {%8,%9}, {%0,%1,%2,%3};"
        : "+f"(c[0]), "+f"(c[1]), "+f"(c[2]), "+f"(c[3])
        : "r"(a0), "r"(a1), "r"(a2), "r"(a3), "r"(b0), "r"(b1));
}

// ---------------- tensor-core GEMM: g_H = A @ W  (A [M,128], W [128,128]) ----------
// block = 256 threads (8 warps). Tile: 128 rows x 128 cols. K chunked by 32.
// Warp w owns rows [w*16, w*16+16) x all 128 cols -> 16 m16n8 acc tiles.
__global__ void __launch_bounds__(256) k_gemm_tc(const float* __restrict__ Aext,
                                                 const float* __restrict__ W,
                                                 int M, int useG) {
    __shared__ uint32_t As[128][PADA];   // tf32 bits, [m][k_local]  (k_local < 32)
    __shared__ uint32_t Ws[32][PADW];    // tf32 bits, [k_local][n]  (n < 128)
    const float* __restrict__ A = useG ? g_G : Aext;

    int tid = threadIdx.x;
    int w = tid >> 5;
    int lane = tid & 31;
    int grp = lane >> 2, t4 = lane & 3;
    int row0 = blockIdx.x * 128;
    int mwarp = w * 16;

    float acc[16][4];
    #pragma unroll
    for (int nt = 0; nt < 16; nt++)
        #pragma unroll
        for (int j = 0; j < 4; j++) acc[nt][j] = 0.f;

    for (int k0 = 0; k0 < CH; k0 += 32) {
        // A chunk: 128 rows x 32 k (float4 loads, tf32 convert)
        #pragma unroll
        for (int p = 0; p < 4; p++) {
            int idx = tid + p * 256;          // 0..1023
            int r = idx >> 3, q = idx & 7;    // 8 float4 per row
            int row = row0 + r;
            float4 v = make_float4(0.f, 0.f, 0.f, 0.f);
            if (row < M) v = *(const float4*)&A[(size_t)row * CH + k0 + q * 4];
            As[r][q * 4 + 0] = f2tf32(v.x);
            As[r][q * 4 + 1] = f2tf32(v.y);
            As[r][q * 4 + 2] = f2tf32(v.z);
            As[r][q * 4 + 3] = f2tf32(v.w);
        }
        // W chunk: 32 k x 128 n  (kept [k][n]; feeds the .col B operand directly)
        #pragma unroll
        for (int p = 0; p < 4; p++) {
            int kl = (tid >> 5) + p * 8;
            int n4 = tid & 31;
            float4 v = *(const float4*)&W[(size_t)(k0 + kl) * CH + n4 * 4];
            uint4 u;
            u.x = f2tf32(v.x); u.y = f2tf32(v.y);
            u.z = f2tf32(v.z); u.w = f2tf32(v.w);
            *(uint4*)&Ws[kl][n4 * 4] = u;
        }
        __syncthreads();

        #pragma unroll
        for (int ks = 0; ks < 4; ks++) {
            int kc = ks * 8;
            uint32_t a0 = As[mwarp + grp][kc + t4];
            uint32_t a1 = As[mwarp + grp + 8][kc + t4];
            uint32_t a2 = As[mwarp + grp][kc + t4 + 4];
            uint32_t a3 = As[mwarp + grp + 8][kc + t4 + 4];
            #pragma unroll
            for (int nt = 0; nt < 16; nt++) {
                uint32_t b0 = Ws[kc + t4][nt * 8 + grp];
                uint32_t b1 = Ws[kc + t4 + 4][nt * 8 + grp];
                mma_tf32(acc[nt], a0, a1, a2, a3, b0, b1);
            }
        }
        __syncthreads();
    }

    // epilogue: c0/c1 -> (row=grp, col=2*t4, 2*t4+1); c2/c3 -> row+8
    int rA = row0 + mwarp + grp;
    int rB = rA + 8;
    #pragma unroll
    for (int nt = 0; nt < 16; nt++) {
        int col = nt * 8 + t4 * 2;
        if (rA < M) *(float2*)&g_H[(size_t)rA * CH + col] = make_float2(acc[nt][0], acc[nt][1]);
        if (rB < M) *(float2*)&g_H[(size_t)rB * CH + col] = make_float2(acc[nt][2], acc[nt][3]);
    }
}

// ---------------- aggregation: warp per node, lane = 4 channels ----------------
// out_i = relu( dis_i * sum_e dis[src]*h[src]  +  h_i/deg_i  +  bias )
__global__ void k_agg(const float* __restrict__ bias, const int* __restrict__ batch,
                      int n, int do_pool) {
    int gw = (blockIdx.x * blockDim.x + threadIdx.x) >> 5;
    int lane = threadIdx.x & 31;
    if (gw >= n) return;
    int i = gw;
    int s = g_off[i];
    int e = s + g_deg[i];
    float ax = 0.f, ay = 0.f, az = 0.f, aw = 0.f;
    int col = lane * 4;
    for (int p = s; p < e; p++) {
        int src = __ldg(&g_csr[p]);
        float wv = __ldg(&g_dis[src]);
        float4 hv = *(const float4*)&g_H[(size_t)src * CH + col];
        ax = fmaf(wv, hv.x, ax);
        ay = fmaf(wv, hv.y, ay);
        az = fmaf(wv, hv.z, az);
        aw = fmaf(wv, hv.w, aw);
    }
    float di = g_dis[i], iv = g_inv[i];
    float4 hi = *(const float4*)&g_H[(size_t)i * CH + col];
    float4 b  = *(const float4*)&bias[col];
    float rx = fmaxf(fmaf(di, ax, fmaf(iv, hi.x, b.x)), 0.f);
    float ry = fmaxf(fmaf(di, ay, fmaf(iv, hi.y, b.y)), 0.f);
    float rz = fmaxf(fmaf(di, az, fmaf(iv, hi.z, b.z)), 0.f);
    float rw = fmaxf(fmaf(di, aw, fmaf(iv, hi.w, b.w)), 0.f);
    if (do_pool) {
        int g = batch[i];
        float* gp = &g_gsum[g * CH + col];
        atomicAdd(gp + 0, rx);
        atomicAdd(gp + 1, ry);
        atomicAdd(gp + 2, rz);
        atomicAdd(gp + 3, rw);
    } else {
        *(float4*)&g_G[(size_t)i * CH + col] = make_float4(rx, ry, rz, rw);
    }
}

// ---------------- final: per-graph mean-pool dot with Wfc ----------------
__global__ void k_final(const float* __restrict__ Wfc, const float* __restrict__ bfc,
                        float* __restrict__ out) {
    int g = (blockIdx.x * blockDim.x + threadIdx.x) >> 5;
    int lane = threadIdx.x & 31;
    if (g >= NGRAPH) return;
    float4 gs = *(const float4*)&g_gsum[g * CH + lane * 4];
    float4 wf = *(const float4*)&Wfc[lane * 4];
    float s = gs.x * wf.x + gs.y * wf.y + gs.z * wf.z + gs.w * wf.w;
    #pragma unroll
    for (int o = 16; o; o >>= 1) s += __shfl_xor_sync(0xFFFFFFFFu, s, o);
    if (lane == 0) {
        float c = (float)(g_gcnt[g] > 1 ? g_gcnt[g] : 1);
        out[g] = s / c + bfc[0];
    }
}

// ---------------- host: single stream, launches only ----------------
extern "C" void kernel_launch(void* const* d_in, const int* in_sizes, int n_in,
                              void* d_out, int out_size) {
    const float* x     = (const float*)d_in[0];
    const int*   ei    = (const int*)  d_in[1];
    const int*   batch = (const int*)  d_in[2];
    const float* W1    = (const float*)d_in[3];
    const float* b1    = (const float*)d_in[4];
    const float* W2    = (const float*)d_in[5];
    const float* b2    = (const float*)d_in[6];
    const float* Wfc   = (const float*)d_in[7];
    const float* bfc   = (const float*)d_in[8];
    float* out = (float*)d_out;

    int n = in_sizes[0] / CH;       // 100000
    int E = in_sizes[1] / 2;        // 1600000
    const int* srcp = ei;
    const int* dstp = ei + E;

    int nb256 = (n + 255) / 256;
    int eb256 = (E + 255) / 256;
    int nbS   = (n + SCAN_B - 1) / SCAN_B;
    int gemm_blocks = (n + 127) / 128;
    int agg_blocks  = (n * 32 + 255) / 256;

    // graph structure (recomputed every launch; deterministic)
    k_init   <<<nb256, 256>>>(n);
    k_count  <<<eb256, 256>>>(dstp, E);
    k_degfin <<<nb256, 256>>>(batch, n);
    k_scan1  <<<nbS, SCAN_B>>>(n);
    k_scan2  <<<1, 256>>>(nbS);
    k_scan3  <<<nb256, 256>>>(n);
    k_scatter<<<eb256, 256>>>(srcp, dstp, E);

    // layer 1: h = x@W1 ; agg+bias+relu -> g_G
    k_gemm_tc<<<gemm_blocks, 256>>>(x, W1, n, 0);
    k_agg    <<<agg_blocks, 256>>>(b1, batch, n, 0);

    // layer 2: h = g_G@W2 ; agg fused with mean-pool accumulate
    k_gemm_tc<<<gemm_blocks, 256>>>(x, W2, n, 1);
    k_agg    <<<agg_blocks, 256>>>(b2, batch, n, 1);

    // readout
    k_final<<<32, 256>>>(Wfc, bfc, out);
}